// round 1
// baseline (speedup 1.0000x reference)
#include <cuda_runtime.h>

// Problem constants
#define T_TOK 2048   // BATCH*SEQ
#define HID   2048
#define INTER 768
#define NEXP  8

// Static device scratch (no runtime allocation allowed)
__device__ int   g_cnt[NEXP];
__device__ int   g_tok[NEXP * T_TOK];
__device__ float g_wt [NEXP * T_TOK];
__device__ float g_hc [(size_t)NEXP * T_TOK * INTER];  // ~50 MB compacted h

// ---------------------------------------------------------------------------
// init: zero output (poisoned by harness) and expert counters
// ---------------------------------------------------------------------------
__global__ void init_kernel(float* __restrict__ out, int n4) {
    int i = blockIdx.x * blockDim.x + threadIdx.x;
    if (i < n4) reinterpret_cast<float4*>(out)[i] = make_float4(0.f, 0.f, 0.f, 0.f);
    if (i < NEXP) g_cnt[i] = 0;
}

// ---------------------------------------------------------------------------
// router: logits -> softmax -> top-2 -> renorm -> compaction
// one block (256 thr) per token
// ---------------------------------------------------------------------------
__global__ void router_kernel(const float* __restrict__ x,
                              const float* __restrict__ wgate) {
    const int t = blockIdx.x;
    const int tid = threadIdx.x;
    const float* xr = x + (size_t)t * HID;

    float part[NEXP];
#pragma unroll
    for (int e = 0; e < NEXP; e++) part[e] = 0.f;

    for (int h = tid; h < HID; h += 256) {
        float xv = xr[h];
#pragma unroll
        for (int e = 0; e < NEXP; e++)
            part[e] += xv * __ldg(&wgate[e * HID + h]);
    }

    __shared__ float red[256];
    __shared__ float logits[NEXP];
#pragma unroll
    for (int e = 0; e < NEXP; e++) {
        red[tid] = part[e];
        __syncthreads();
        for (int s = 128; s > 0; s >>= 1) {
            if (tid < s) red[tid] += red[tid + s];
            __syncthreads();
        }
        if (tid == 0) logits[e] = red[0];
        __syncthreads();
    }

    if (tid == 0) {
        float mx = logits[0];
#pragma unroll
        for (int e = 1; e < NEXP; e++) mx = fmaxf(mx, logits[e]);
        float p[NEXP], s = 0.f;
#pragma unroll
        for (int e = 0; e < NEXP; e++) { p[e] = expf(logits[e] - mx); s += p[e]; }
        float inv = 1.f / s;
#pragma unroll
        for (int e = 0; e < NEXP; e++) p[e] *= inv;

        // top-2, ties -> lower index (matches lax.top_k)
        int e1 = 0;
#pragma unroll
        for (int e = 1; e < NEXP; e++) if (p[e] > p[e1]) e1 = e;
        int e2 = (e1 == 0) ? 1 : 0;
#pragma unroll
        for (int e = 0; e < NEXP; e++)
            if (e != e1 && p[e] > p[e2]) e2 = e;

        float w1 = p[e1], w2 = p[e2];
        float rs = 1.f / (w1 + w2);
        w1 *= rs; w2 *= rs;

        int s1 = atomicAdd(&g_cnt[e1], 1);
        g_tok[e1 * T_TOK + s1] = t;
        g_wt [e1 * T_TOK + s1] = w1;
        int s2 = atomicAdd(&g_cnt[e2], 1);
        g_tok[e2 * T_TOK + s2] = t;
        g_wt [e2 * T_TOK + s2] = w2;
    }
}

// ---------------------------------------------------------------------------
// gemm1: h[row, :] = wt[row] * silu(x[tok] @ Wg_e) * (x[tok] @ Wu_e)
// 64x64x16 fp32 SIMT tile, 256 threads, 4x4 per thread, dual-B (gate+up)
// grid: (INTER/64, T_TOK/64, NEXP)
// ---------------------------------------------------------------------------
#define BM 64
#define BN 64
#define BK 16

__global__ __launch_bounds__(256) void gemm1_kernel(
    const float* __restrict__ x,
    const float* __restrict__ Wg,
    const float* __restrict__ Wu) {
    const int e = blockIdx.z;
    const int rows = g_cnt[e];
    const int m0 = blockIdx.y * BM;
    if (m0 >= rows) return;
    const int n0 = blockIdx.x * BN;

    __shared__ float sA[BK][BM];
    __shared__ float sG[BK][BN];
    __shared__ float sU[BK][BN];
    __shared__ int   stok[BM];
    __shared__ float swt[BM];

    const int tid = threadIdx.x;
    if (tid < BM) {
        int gm = m0 + tid;
        int tk = 0; float w = 0.f;
        if (gm < rows) { tk = g_tok[e * T_TOK + gm]; w = g_wt[e * T_TOK + gm]; }
        stok[tid] = tk; swt[tid] = w;
    }
    __syncthreads();

    const int tx = tid & 15, ty = tid >> 4;
    float accg[4][4] = {}, accu[4][4] = {};

    const int lm = tid >> 2;          // 0..63 : A row
    const int lk = (tid & 3) * 4;     // 0,4,8,12 : A k-slab
    const int bk = tid >> 4;          // 0..15 : B k row
    const int bn = (tid & 15) * 4;    // B n-slab

    const float* xrow = x + (size_t)stok[lm] * HID;
    const float* wgB = Wg + (size_t)e * HID * INTER + n0;
    const float* wuB = Wu + (size_t)e * HID * INTER + n0;

    for (int kk = 0; kk < HID; kk += BK) {
        float4 av = *reinterpret_cast<const float4*>(xrow + kk + lk);
        sA[lk + 0][lm] = av.x; sA[lk + 1][lm] = av.y;
        sA[lk + 2][lm] = av.z; sA[lk + 3][lm] = av.w;
        *reinterpret_cast<float4*>(&sG[bk][bn]) =
            *reinterpret_cast<const float4*>(wgB + (size_t)(kk + bk) * INTER + bn);
        *reinterpret_cast<float4*>(&sU[bk][bn]) =
            *reinterpret_cast<const float4*>(wuB + (size_t)(kk + bk) * INTER + bn);
        __syncthreads();

#pragma unroll
        for (int k = 0; k < BK; k++) {
            float4 a  = *reinterpret_cast<const float4*>(&sA[k][ty * 4]);
            float4 bg = *reinterpret_cast<const float4*>(&sG[k][tx * 4]);
            float4 bu = *reinterpret_cast<const float4*>(&sU[k][tx * 4]);
            float aa[4] = {a.x, a.y, a.z, a.w};
            float gg[4] = {bg.x, bg.y, bg.z, bg.w};
            float uu[4] = {bu.x, bu.y, bu.z, bu.w};
#pragma unroll
            for (int i = 0; i < 4; i++)
#pragma unroll
                for (int j = 0; j < 4; j++) {
                    accg[i][j] += aa[i] * gg[j];
                    accu[i][j] += aa[i] * uu[j];
                }
        }
        __syncthreads();
    }

    float* hbase = g_hc + (size_t)e * T_TOK * INTER;
#pragma unroll
    for (int i = 0; i < 4; i++) {
        int gm = m0 + ty * 4 + i;
        if (gm < rows) {
            float w = swt[ty * 4 + i];
            float v[4];
#pragma unroll
            for (int j = 0; j < 4; j++) {
                float g = accg[i][j];
                float u = accu[i][j];
                float s = g / (1.f + expf(-g));   // silu
                v[j] = s * u * w;
            }
            *reinterpret_cast<float4*>(hbase + (size_t)gm * INTER + n0 + tx * 4) =
                make_float4(v[0], v[1], v[2], v[3]);
        }
    }
}

// ---------------------------------------------------------------------------
// gemm2: out[tok, :] += h[row, :] @ Wd_e   (weight already folded into h)
// grid: (HID/64, T_TOK/64, NEXP)
// ---------------------------------------------------------------------------
__global__ __launch_bounds__(256) void gemm2_kernel(
    const float* __restrict__ Wd,
    float* __restrict__ out) {
    const int e = blockIdx.z;
    const int rows = g_cnt[e];
    const int m0 = blockIdx.y * BM;
    if (m0 >= rows) return;
    const int n0 = blockIdx.x * BN;

    __shared__ float sA[BK][BM];
    __shared__ float sB[BK][BN];
    __shared__ int   stok[BM];

    const int tid = threadIdx.x;
    if (tid < BM) {
        int gm = m0 + tid;
        stok[tid] = (gm < rows) ? g_tok[e * T_TOK + gm] : 0;
    }
    __syncthreads();

    const int tx = tid & 15, ty = tid >> 4;
    float acc[4][4] = {};

    const int lm = tid >> 2;
    const int lk = (tid & 3) * 4;
    const int bk = tid >> 4;
    const int bn = (tid & 15) * 4;

    const float* arow = g_hc + ((size_t)e * T_TOK + m0 + lm) * INTER;
    const float* wdB = Wd + (size_t)e * INTER * HID + n0;

    for (int kk = 0; kk < INTER; kk += BK) {
        float4 av = *reinterpret_cast<const float4*>(arow + kk + lk);
        sA[lk + 0][lm] = av.x; sA[lk + 1][lm] = av.y;
        sA[lk + 2][lm] = av.z; sA[lk + 3][lm] = av.w;
        *reinterpret_cast<float4*>(&sB[bk][bn]) =
            *reinterpret_cast<const float4*>(wdB + (size_t)(kk + bk) * HID + bn);
        __syncthreads();

#pragma unroll
        for (int k = 0; k < BK; k++) {
            float4 a = *reinterpret_cast<const float4*>(&sA[k][ty * 4]);
            float4 b = *reinterpret_cast<const float4*>(&sB[k][tx * 4]);
            float aa[4] = {a.x, a.y, a.z, a.w};
            float bb[4] = {b.x, b.y, b.z, b.w};
#pragma unroll
            for (int i = 0; i < 4; i++)
#pragma unroll
                for (int j = 0; j < 4; j++)
                    acc[i][j] += aa[i] * bb[j];
        }
        __syncthreads();
    }

#pragma unroll
    for (int i = 0; i < 4; i++) {
        int gm = m0 + ty * 4 + i;
        if (gm < rows) {
            int t = stok[ty * 4 + i];
            float* orow = out + (size_t)t * HID + n0 + tx * 4;
#pragma unroll
            for (int j = 0; j < 4; j++)
                atomicAdd(orow + j, acc[i][j]);
        }
    }
}

// ---------------------------------------------------------------------------
// launch
// ---------------------------------------------------------------------------
extern "C" void kernel_launch(void* const* d_in, const int* in_sizes, int n_in,
                              void* d_out, int out_size) {
    const float* x     = (const float*)d_in[0];  // [B,S,H] -> [T,H]
    const float* wgate = (const float*)d_in[1];  // [E,H]
    const float* Wg    = (const float*)d_in[2];  // [E,H,I]
    const float* Wu    = (const float*)d_in[3];  // [E,H,I]
    const float* Wd    = (const float*)d_in[4];  // [E,I,H]
    float* out = (float*)d_out;                  // [T,H]

    // 1) zero output + counters
    int n4 = (T_TOK * HID) / 4;
    init_kernel<<<(n4 + 255) / 256, 256>>>(out, n4);

    // 2) router + compaction
    router_kernel<<<T_TOK, 256>>>(x, wgate);

    // 3) fused gate/up GEMM + SiLU*up*weight -> compacted h
    dim3 g1(INTER / BN, T_TOK / BM, NEXP);
    gemm1_kernel<<<g1, 256>>>(x, Wg, Wu);

    // 4) down GEMM, atomic scatter-add into out
    dim3 g2(HID / BN, T_TOK / BM, NEXP);
    gemm2_kernel<<<g2, 256>>>(Wd, out);
}

// round 2
// speedup vs baseline: 1.7651x; 1.7651x over previous
#include <cuda_runtime.h>

// Problem constants
#define T_TOK 2048   // BATCH*SEQ
#define HID   2048
#define INTER 768
#define NEXP  8

// GEMM tiling
#define BM 64
#define BN 64
#define BK 32
#define SAP (BM + 8)   // padded smem strides (conflict-free frag loads)
#define SBP (BN + 8)

// Static device scratch (no runtime allocation allowed)
__device__ int   g_cnt[NEXP];
__device__ int   g_tok[NEXP * T_TOK];
__device__ float g_wt [NEXP * T_TOK];
__device__ float g_hc [(size_t)NEXP * T_TOK * INTER];  // ~50 MB compacted h

__device__ __forceinline__ float to_tf32(float x) {
    float y;
    asm("cvt.rna.tf32.f32 %0, %1;" : "=f"(y) : "f"(x));
    return y;
}

__device__ __forceinline__ void mma_tf32(float* d, const unsigned* a, const unsigned* b) {
    asm volatile(
        "mma.sync.aligned.m16n8k8.row.col.f32.tf32.tf32.f32 "
        "{%0,%1,%2,%3},{%4,%5,%6,%7},{%8,%9},{%0,%1,%2,%3};"
        : "+f"(d[0]), "+f"(d[1]), "+f"(d[2]), "+f"(d[3])
        : "r"(a[0]), "r"(a[1]), "r"(a[2]), "r"(a[3]), "r"(b[0]), "r"(b[1]));
}

// ---------------------------------------------------------------------------
// init: zero output (poisoned by harness) and expert counters
// ---------------------------------------------------------------------------
__global__ void init_kernel(float* __restrict__ out, int n4) {
    int i = blockIdx.x * blockDim.x + threadIdx.x;
    if (i < n4) reinterpret_cast<float4*>(out)[i] = make_float4(0.f, 0.f, 0.f, 0.f);
    if (i < NEXP) g_cnt[i] = 0;
}

// ---------------------------------------------------------------------------
// router: logits -> softmax -> top-2 -> renorm -> compaction (exact fp32)
// ---------------------------------------------------------------------------
__global__ void router_kernel(const float* __restrict__ x,
                              const float* __restrict__ wgate) {
    const int t = blockIdx.x;
    const int tid = threadIdx.x;
    const float* xr = x + (size_t)t * HID;

    float part[NEXP];
#pragma unroll
    for (int e = 0; e < NEXP; e++) part[e] = 0.f;

    for (int h = tid; h < HID; h += 256) {
        float xv = xr[h];
#pragma unroll
        for (int e = 0; e < NEXP; e++)
            part[e] += xv * __ldg(&wgate[e * HID + h]);
    }

    __shared__ float red[256];
    __shared__ float logits[NEXP];
#pragma unroll
    for (int e = 0; e < NEXP; e++) {
        red[tid] = part[e];
        __syncthreads();
        for (int s = 128; s > 0; s >>= 1) {
            if (tid < s) red[tid] += red[tid + s];
            __syncthreads();
        }
        if (tid == 0) logits[e] = red[0];
        __syncthreads();
    }

    if (tid == 0) {
        float mx = logits[0];
#pragma unroll
        for (int e = 1; e < NEXP; e++) mx = fmaxf(mx, logits[e]);
        float p[NEXP], s = 0.f;
#pragma unroll
        for (int e = 0; e < NEXP; e++) { p[e] = expf(logits[e] - mx); s += p[e]; }
        float inv = 1.f / s;
#pragma unroll
        for (int e = 0; e < NEXP; e++) p[e] *= inv;

        int e1 = 0;
#pragma unroll
        for (int e = 1; e < NEXP; e++) if (p[e] > p[e1]) e1 = e;
        int e2 = (e1 == 0) ? 1 : 0;
#pragma unroll
        for (int e = 0; e < NEXP; e++)
            if (e != e1 && p[e] > p[e2]) e2 = e;

        float w1 = p[e1], w2 = p[e2];
        float rs = 1.f / (w1 + w2);
        w1 *= rs; w2 *= rs;

        int s1 = atomicAdd(&g_cnt[e1], 1);
        g_tok[e1 * T_TOK + s1] = t;
        g_wt [e1 * T_TOK + s1] = w1;
        int s2 = atomicAdd(&g_cnt[e2], 1);
        g_tok[e2 * T_TOK + s2] = t;
        g_wt [e2 * T_TOK + s2] = w2;
    }
}

// ---------------------------------------------------------------------------
// gemm1 (tf32 tensor cores): h = wt * silu(x@Wg) * (x@Wu), compacted rows
// 64x64x32 block, 8 warps (2m x 4n), warp tile 32x16 (2x2 m16n8k8 frags)
// ---------------------------------------------------------------------------
__global__ __launch_bounds__(256) void gemm1_kernel(
    const float* __restrict__ x,
    const float* __restrict__ Wg,
    const float* __restrict__ Wu) {
    const int e = blockIdx.z;
    const int rows = g_cnt[e];
    const int m0 = blockIdx.y * BM;
    if (m0 >= rows) return;
    const int n0 = blockIdx.x * BN;

    __shared__ __align__(16) float sA[BK][SAP];
    __shared__ __align__(16) float sG[BK][SBP];
    __shared__ __align__(16) float sU[BK][SBP];
    __shared__ int   stok[BM];
    __shared__ float swt[BM];

    const int tid = threadIdx.x;
    if (tid < BM) {
        int gm = m0 + tid;
        int tk = 0; float w = 0.f;
        if (gm < rows) { tk = g_tok[e * T_TOK + gm]; w = g_wt[e * T_TOK + gm]; }
        stok[tid] = tk; swt[tid] = w;
    }
    __syncthreads();

    // loader indices
    const int lm  = tid & 63;    // A row
    const int lk4 = tid >> 6;    // 0..3
    const int bk  = tid >> 4;    // 0..15 (B k row, +16 for second)
    const int bn  = (tid & 15) * 4;

    const float* xrow = x + (size_t)stok[lm] * HID;
    const float* wgB = Wg + (size_t)e * HID * INTER + n0;
    const float* wuB = Wu + (size_t)e * HID * INTER + n0;

    const int lane = tid & 31;
    const int warp = tid >> 5;
    const int wm = (warp & 1) * 32;   // warp m base
    const int wn = (warp >> 1) * 16;  // warp n base
    const int gid = lane >> 2, tg = lane & 3;

    float accG[2][2][4] = {};
    float accU[2][2][4] = {};

    for (int kk = 0; kk < HID; kk += BK) {
        // A: gathered token rows, transpose into sA[k][m] with tf32 rounding
#pragma unroll
        for (int s = 0; s < 2; s++) {
            int kq = (lk4 + s * 4) * 4;
            float4 v = *reinterpret_cast<const float4*>(xrow + kk + kq);
            sA[kq + 0][lm] = to_tf32(v.x);
            sA[kq + 1][lm] = to_tf32(v.y);
            sA[kq + 2][lm] = to_tf32(v.z);
            sA[kq + 3][lm] = to_tf32(v.w);
        }
        // B tiles (gate + up), row-major K x N
#pragma unroll
        for (int s = 0; s < 2; s++) {
            int kr = bk + s * 16;
            float4 g4 = *reinterpret_cast<const float4*>(wgB + (size_t)(kk + kr) * INTER + bn);
            float4 u4 = *reinterpret_cast<const float4*>(wuB + (size_t)(kk + kr) * INTER + bn);
            g4.x = to_tf32(g4.x); g4.y = to_tf32(g4.y); g4.z = to_tf32(g4.z); g4.w = to_tf32(g4.w);
            u4.x = to_tf32(u4.x); u4.y = to_tf32(u4.y); u4.z = to_tf32(u4.z); u4.w = to_tf32(u4.w);
            *reinterpret_cast<float4*>(&sG[kr][bn]) = g4;
            *reinterpret_cast<float4*>(&sU[kr][bn]) = u4;
        }
        __syncthreads();

#pragma unroll
        for (int k8 = 0; k8 < BK; k8 += 8) {
            unsigned a[2][4];
#pragma unroll
            for (int f = 0; f < 2; f++) {
                int r0 = wm + f * 16 + gid;
                a[f][0] = __float_as_uint(sA[k8 + tg    ][r0    ]);
                a[f][1] = __float_as_uint(sA[k8 + tg    ][r0 + 8]);
                a[f][2] = __float_as_uint(sA[k8 + tg + 4][r0    ]);
                a[f][3] = __float_as_uint(sA[k8 + tg + 4][r0 + 8]);
            }
            unsigned bg[2][2], bu[2][2];
#pragma unroll
            for (int j = 0; j < 2; j++) {
                int c = wn + j * 8 + gid;
                bg[j][0] = __float_as_uint(sG[k8 + tg    ][c]);
                bg[j][1] = __float_as_uint(sG[k8 + tg + 4][c]);
                bu[j][0] = __float_as_uint(sU[k8 + tg    ][c]);
                bu[j][1] = __float_as_uint(sU[k8 + tg + 4][c]);
            }
#pragma unroll
            for (int f = 0; f < 2; f++)
#pragma unroll
                for (int j = 0; j < 2; j++) {
                    mma_tf32(accG[f][j], a[f], bg[j]);
                    mma_tf32(accU[f][j], a[f], bu[j]);
                }
        }
        __syncthreads();
    }

    // epilogue: silu(g)*u*w -> g_hc
    float* hbase = g_hc + (size_t)e * T_TOK * INTER;
#pragma unroll
    for (int f = 0; f < 2; f++) {
#pragma unroll
        for (int half = 0; half < 2; half++) {
            int rm = wm + f * 16 + gid + half * 8;
            int gm = m0 + rm;
            if (gm < rows) {
                float w = swt[rm];
#pragma unroll
                for (int j = 0; j < 2; j++) {
                    float g0 = accG[f][j][half * 2 + 0];
                    float g1 = accG[f][j][half * 2 + 1];
                    float u0 = accU[f][j][half * 2 + 0];
                    float u1 = accU[f][j][half * 2 + 1];
                    float s0 = g0 / (1.f + expf(-g0)) * u0 * w;
                    float s1 = g1 / (1.f + expf(-g1)) * u1 * w;
                    int col = n0 + wn + j * 8 + 2 * tg;
                    *reinterpret_cast<float2*>(hbase + (size_t)gm * INTER + col) =
                        make_float2(s0, s1);
                }
            }
        }
    }
}

// ---------------------------------------------------------------------------
// gemm2 (tf32 tensor cores): out[tok,:] += h @ Wd_e  (atomic scatter)
// ---------------------------------------------------------------------------
__global__ __launch_bounds__(256) void gemm2_kernel(
    const float* __restrict__ Wd,
    float* __restrict__ out) {
    const int e = blockIdx.z;
    const int rows = g_cnt[e];
    const int m0 = blockIdx.y * BM;
    if (m0 >= rows) return;
    const int n0 = blockIdx.x * BN;

    __shared__ __align__(16) float sA[BK][SAP];
    __shared__ __align__(16) float sB[BK][SBP];
    __shared__ int stok[BM];

    const int tid = threadIdx.x;
    if (tid < BM) {
        int gm = m0 + tid;
        stok[tid] = (gm < rows) ? g_tok[e * T_TOK + gm] : 0;
    }
    __syncthreads();

    const int lm  = tid & 63;
    const int lk4 = tid >> 6;
    const int bk  = tid >> 4;
    const int bn  = (tid & 15) * 4;

    const float* arow = g_hc + ((size_t)e * T_TOK + m0 + lm) * INTER;
    const float* wdB = Wd + (size_t)e * INTER * HID + n0;

    const int lane = tid & 31;
    const int warp = tid >> 5;
    const int wm = (warp & 1) * 32;
    const int wn = (warp >> 1) * 16;
    const int gid = lane >> 2, tg = lane & 3;

    float acc[2][2][4] = {};

    for (int kk = 0; kk < INTER; kk += BK) {
#pragma unroll
        for (int s = 0; s < 2; s++) {
            int kq = (lk4 + s * 4) * 4;
            float4 v = *reinterpret_cast<const float4*>(arow + kk + kq);
            sA[kq + 0][lm] = to_tf32(v.x);
            sA[kq + 1][lm] = to_tf32(v.y);
            sA[kq + 2][lm] = to_tf32(v.z);
            sA[kq + 3][lm] = to_tf32(v.w);
        }
#pragma unroll
        for (int s = 0; s < 2; s++) {
            int kr = bk + s * 16;
            float4 b4 = *reinterpret_cast<const float4*>(wdB + (size_t)(kk + kr) * HID + bn);
            b4.x = to_tf32(b4.x); b4.y = to_tf32(b4.y); b4.z = to_tf32(b4.z); b4.w = to_tf32(b4.w);
            *reinterpret_cast<float4*>(&sB[kr][bn]) = b4;
        }
        __syncthreads();

#pragma unroll
        for (int k8 = 0; k8 < BK; k8 += 8) {
            unsigned a[2][4];
#pragma unroll
            for (int f = 0; f < 2; f++) {
                int r0 = wm + f * 16 + gid;
                a[f][0] = __float_as_uint(sA[k8 + tg    ][r0    ]);
                a[f][1] = __float_as_uint(sA[k8 + tg    ][r0 + 8]);
                a[f][2] = __float_as_uint(sA[k8 + tg + 4][r0    ]);
                a[f][3] = __float_as_uint(sA[k8 + tg + 4][r0 + 8]);
            }
            unsigned b[2][2];
#pragma unroll
            for (int j = 0; j < 2; j++) {
                int c = wn + j * 8 + gid;
                b[j][0] = __float_as_uint(sB[k8 + tg    ][c]);
                b[j][1] = __float_as_uint(sB[k8 + tg + 4][c]);
            }
#pragma unroll
            for (int f = 0; f < 2; f++)
#pragma unroll
                for (int j = 0; j < 2; j++)
                    mma_tf32(acc[f][j], a[f], b[j]);
        }
        __syncthreads();
    }

#pragma unroll
    for (int f = 0; f < 2; f++) {
#pragma unroll
        for (int half = 0; half < 2; half++) {
            int rm = wm + f * 16 + gid + half * 8;
            int gm = m0 + rm;
            if (gm < rows) {
                int t = stok[rm];
                float* orow = out + (size_t)t * HID;
#pragma unroll
                for (int j = 0; j < 2; j++) {
                    int col = n0 + wn + j * 8 + 2 * tg;
                    atomicAdd(orow + col,     acc[f][j][half * 2 + 0]);
                    atomicAdd(orow + col + 1, acc[f][j][half * 2 + 1]);
                }
            }
        }
    }
}

// ---------------------------------------------------------------------------
// launch
// ---------------------------------------------------------------------------
extern "C" void kernel_launch(void* const* d_in, const int* in_sizes, int n_in,
                              void* d_out, int out_size) {
    const float* x     = (const float*)d_in[0];
    const float* wgate = (const float*)d_in[1];
    const float* Wg    = (const float*)d_in[2];
    const float* Wu    = (const float*)d_in[3];
    const float* Wd    = (const float*)d_in[4];
    float* out = (float*)d_out;

    int n4 = (T_TOK * HID) / 4;
    init_kernel<<<(n4 + 255) / 256, 256>>>(out, n4);

    router_kernel<<<T_TOK, 256>>>(x, wgate);

    dim3 g1(INTER / BN, T_TOK / BM, NEXP);
    gemm1_kernel<<<g1, 256>>>(x, Wg, Wu);

    dim3 g2(HID / BN, T_TOK / BM, NEXP);
    gemm2_kernel<<<g2, 256>>>(Wd, out);
}

// round 3
// speedup vs baseline: 1.7728x; 1.0044x over previous
#include <cuda_runtime.h>

// Problem constants
#define T_TOK 2048   // BATCH*SEQ
#define HID   2048
#define INTER 768
#define NEXP  8

// GEMM tiling
#define BM 64
#define BN 64
#define BK 32
#define SAP (BM + 8)   // padded smem strides (conflict-free frag loads)
#define SBP (BN + 8)

// Static device scratch (no runtime allocation allowed)
__device__ int   g_cnt[NEXP];
__device__ int   g_tok[NEXP * T_TOK];
__device__ float g_wt [NEXP * T_TOK];
__device__ float g_hc [(size_t)NEXP * T_TOK * INTER];  // ~50 MB compacted h

__device__ __forceinline__ float to_tf32(float x) {
    float y;
    asm("cvt.rna.tf32.f32 %0, %1;" : "=f"(y) : "f"(x));
    return y;
}

__device__ __forceinline__ void mma_tf32(float* d, const unsigned* a, const unsigned* b) {
    asm volatile(
        "mma.sync.aligned.m16n8k8.row.col.f32.tf32.tf32.f32 "
        "{%0,%1,%2,%3},{%4,%5,%6,%7},{%8,%9},{%0,%1,%2,%3};"
        : "+f"(d[0]), "+f"(d[1]), "+f"(d[2]), "+f"(d[3])
        : "r"(a[0]), "r"(a[1]), "r"(a[2]), "r"(a[3]), "r"(b[0]), "r"(b[1]));
}

// ---------------------------------------------------------------------------
// init: zero output (poisoned by harness) and expert counters
// ---------------------------------------------------------------------------
__global__ void init_kernel(float* __restrict__ out, int n4) {
    int i = blockIdx.x * blockDim.x + threadIdx.x;
    if (i < n4) reinterpret_cast<float4*>(out)[i] = make_float4(0.f, 0.f, 0.f, 0.f);
    if (i < NEXP) g_cnt[i] = 0;
}

// ---------------------------------------------------------------------------
// router: logits -> softmax -> top-2 -> renorm -> compaction (exact fp32)
// ---------------------------------------------------------------------------
__global__ void router_kernel(const float* __restrict__ x,
                              const float* __restrict__ wgate) {
    const int t = blockIdx.x;
    const int tid = threadIdx.x;
    const float* xr = x + (size_t)t * HID;

    float part[NEXP];
#pragma unroll
    for (int e = 0; e < NEXP; e++) part[e] = 0.f;

    for (int h = tid; h < HID; h += 256) {
        float xv = xr[h];
#pragma unroll
        for (int e = 0; e < NEXP; e++)
            part[e] += xv * __ldg(&wgate[e * HID + h]);
    }

    __shared__ float red[256];
    __shared__ float logits[NEXP];
#pragma unroll
    for (int e = 0; e < NEXP; e++) {
        red[tid] = part[e];
        __syncthreads();
        for (int s = 128; s > 0; s >>= 1) {
            if (tid < s) red[tid] += red[tid + s];
            __syncthreads();
        }
        if (tid == 0) logits[e] = red[0];
        __syncthreads();
    }

    if (tid == 0) {
        float mx = logits[0];
#pragma unroll
        for (int e = 1; e < NEXP; e++) mx = fmaxf(mx, logits[e]);
        float p[NEXP], s = 0.f;
#pragma unroll
        for (int e = 0; e < NEXP; e++) { p[e] = expf(logits[e] - mx); s += p[e]; }
        float inv = 1.f / s;
#pragma unroll
        for (int e = 0; e < NEXP; e++) p[e] *= inv;

        int e1 = 0;
#pragma unroll
        for (int e = 1; e < NEXP; e++) if (p[e] > p[e1]) e1 = e;
        int e2 = (e1 == 0) ? 1 : 0;
#pragma unroll
        for (int e = 0; e < NEXP; e++)
            if (e != e1 && p[e] > p[e2]) e2 = e;

        float w1 = p[e1], w2 = p[e2];
        float rs = 1.f / (w1 + w2);
        w1 *= rs; w2 *= rs;

        int s1 = atomicAdd(&g_cnt[e1], 1);
        g_tok[e1 * T_TOK + s1] = t;
        g_wt [e1 * T_TOK + s1] = w1;
        int s2 = atomicAdd(&g_cnt[e2], 1);
        g_tok[e2 * T_TOK + s2] = t;
        g_wt [e2 * T_TOK + s2] = w2;
    }
}

// ---------------------------------------------------------------------------
// gemm1 (tf32 tensor cores): h = wt * silu(x@Wg) * (x@Wu), compacted rows
// 64x64x32 block, 8 warps (2m x 4n), warp tile 32x16 (2x2 m16n8k8 frags)
// ---------------------------------------------------------------------------
__global__ __launch_bounds__(256) void gemm1_kernel(
    const float* __restrict__ x,
    const float* __restrict__ Wg,
    const float* __restrict__ Wu) {
    const int e = blockIdx.z;
    const int rows = g_cnt[e];
    const int m0 = blockIdx.y * BM;
    if (m0 >= rows) return;
    const int n0 = blockIdx.x * BN;

    __shared__ __align__(16) float sA[BK][SAP];
    __shared__ __align__(16) float sG[BK][SBP];
    __shared__ __align__(16) float sU[BK][SBP];
    __shared__ int   stok[BM];
    __shared__ float swt[BM];

    const int tid = threadIdx.x;
    if (tid < BM) {
        int gm = m0 + tid;
        int tk = 0; float w = 0.f;
        if (gm < rows) { tk = g_tok[e * T_TOK + gm]; w = g_wt[e * T_TOK + gm]; }
        stok[tid] = tk; swt[tid] = w;
    }
    __syncthreads();

    // loader indices
    const int lm  = tid & 63;    // A row
    const int lk4 = tid >> 6;    // 0..3
    const int bk  = tid >> 4;    // 0..15 (B k row, +16 for second)
    const int bn  = (tid & 15) * 4;

    const float* xrow = x + (size_t)stok[lm] * HID;
    const float* wgB = Wg + (size_t)e * HID * INTER + n0;
    const float* wuB = Wu + (size_t)e * HID * INTER + n0;

    const int lane = tid & 31;
    const int warp = tid >> 5;
    const int wm = (warp & 1) * 32;   // warp m base
    const int wn = (warp >> 1) * 16;  // warp n base
    const int gid = lane >> 2, tg = lane & 3;

    float accG[2][2][4] = {};
    float accU[2][2][4] = {};

    for (int kk = 0; kk < HID; kk += BK) {
        // A: gathered token rows, transpose into sA[k][m] with tf32 rounding
#pragma unroll
        for (int s = 0; s < 2; s++) {
            int kq = (lk4 + s * 4) * 4;
            float4 v = *reinterpret_cast<const float4*>(xrow + kk + kq);
            sA[kq + 0][lm] = to_tf32(v.x);
            sA[kq + 1][lm] = to_tf32(v.y);
            sA[kq + 2][lm] = to_tf32(v.z);
            sA[kq + 3][lm] = to_tf32(v.w);
        }
        // B tiles (gate + up), row-major K x N
#pragma unroll
        for (int s = 0; s < 2; s++) {
            int kr = bk + s * 16;
            float4 g4 = *reinterpret_cast<const float4*>(wgB + (size_t)(kk + kr) * INTER + bn);
            float4 u4 = *reinterpret_cast<const float4*>(wuB + (size_t)(kk + kr) * INTER + bn);
            g4.x = to_tf32(g4.x); g4.y = to_tf32(g4.y); g4.z = to_tf32(g4.z); g4.w = to_tf32(g4.w);
            u4.x = to_tf32(u4.x); u4.y = to_tf32(u4.y); u4.z = to_tf32(u4.z); u4.w = to_tf32(u4.w);
            *reinterpret_cast<float4*>(&sG[kr][bn]) = g4;
            *reinterpret_cast<float4*>(&sU[kr][bn]) = u4;
        }
        __syncthreads();

#pragma unroll
        for (int k8 = 0; k8 < BK; k8 += 8) {
            unsigned a[2][4];
#pragma unroll
            for (int f = 0; f < 2; f++) {
                int r0 = wm + f * 16 + gid;
                a[f][0] = __float_as_uint(sA[k8 + tg    ][r0    ]);
                a[f][1] = __float_as_uint(sA[k8 + tg    ][r0 + 8]);
                a[f][2] = __float_as_uint(sA[k8 + tg + 4][r0    ]);
                a[f][3] = __float_as_uint(sA[k8 + tg + 4][r0 + 8]);
            }
            unsigned bg[2][2], bu[2][2];
#pragma unroll
            for (int j = 0; j < 2; j++) {
                int c = wn + j * 8 + gid;
                bg[j][0] = __float_as_uint(sG[k8 + tg    ][c]);
                bg[j][1] = __float_as_uint(sG[k8 + tg + 4][c]);
                bu[j][0] = __float_as_uint(sU[k8 + tg    ][c]);
                bu[j][1] = __float_as_uint(sU[k8 + tg + 4][c]);
            }
#pragma unroll
            for (int f = 0; f < 2; f++)
#pragma unroll
                for (int j = 0; j < 2; j++) {
                    mma_tf32(accG[f][j], a[f], bg[j]);
                    mma_tf32(accU[f][j], a[f], bu[j]);
                }
        }
        __syncthreads();
    }

    // epilogue: silu(g)*u*w -> g_hc
    float* hbase = g_hc + (size_t)e * T_TOK * INTER;
#pragma unroll
    for (int f = 0; f < 2; f++) {
#pragma unroll
        for (int half = 0; half < 2; half++) {
            int rm = wm + f * 16 + gid + half * 8;
            int gm = m0 + rm;
            if (gm < rows) {
                float w = swt[rm];
#pragma unroll
                for (int j = 0; j < 2; j++) {
                    float g0 = accG[f][j][half * 2 + 0];
                    float g1 = accG[f][j][half * 2 + 1];
                    float u0 = accU[f][j][half * 2 + 0];
                    float u1 = accU[f][j][half * 2 + 1];
                    float s0 = g0 / (1.f + expf(-g0)) * u0 * w;
                    float s1 = g1 / (1.f + expf(-g1)) * u1 * w;
                    int col = n0 + wn + j * 8 + 2 * tg;
                    *reinterpret_cast<float2*>(hbase + (size_t)gm * INTER + col) =
                        make_float2(s0, s1);
                }
            }
        }
    }
}

// ---------------------------------------------------------------------------
// gemm2 (tf32 tensor cores): out[tok,:] += h @ Wd_e  (atomic scatter)
// ---------------------------------------------------------------------------
__global__ __launch_bounds__(256) void gemm2_kernel(
    const float* __restrict__ Wd,
    float* __restrict__ out) {
    const int e = blockIdx.z;
    const int rows = g_cnt[e];
    const int m0 = blockIdx.y * BM;
    if (m0 >= rows) return;
    const int n0 = blockIdx.x * BN;

    __shared__ __align__(16) float sA[BK][SAP];
    __shared__ __align__(16) float sB[BK][SBP];
    __shared__ int stok[BM];

    const int tid = threadIdx.x;
    if (tid < BM) {
        int gm = m0 + tid;
        stok[tid] = (gm < rows) ? g_tok[e * T_TOK + gm] : 0;
    }
    __syncthreads();

    const int lm  = tid & 63;
    const int lk4 = tid >> 6;
    const int bk  = tid >> 4;
    const int bn  = (tid & 15) * 4;

    const float* arow = g_hc + ((size_t)e * T_TOK + m0 + lm) * INTER;
    const float* wdB = Wd + (size_t)e * INTER * HID + n0;

    const int lane = tid & 31;
    const int warp = tid >> 5;
    const int wm = (warp & 1) * 32;
    const int wn = (warp >> 1) * 16;
    const int gid = lane >> 2, tg = lane & 3;

    float acc[2][2][4] = {};

    for (int kk = 0; kk < INTER; kk += BK) {
#pragma unroll
        for (int s = 0; s < 2; s++) {
            int kq = (lk4 + s * 4) * 4;
            float4 v = *reinterpret_cast<const float4*>(arow + kk + kq);
            sA[kq + 0][lm] = to_tf32(v.x);
            sA[kq + 1][lm] = to_tf32(v.y);
            sA[kq + 2][lm] = to_tf32(v.z);
            sA[kq + 3][lm] = to_tf32(v.w);
        }
#pragma unroll
        for (int s = 0; s < 2; s++) {
            int kr = bk + s * 16;
            float4 b4 = *reinterpret_cast<const float4*>(wdB + (size_t)(kk + kr) * HID + bn);
            b4.x = to_tf32(b4.x); b4.y = to_tf32(b4.y); b4.z = to_tf32(b4.z); b4.w = to_tf32(b4.w);
            *reinterpret_cast<float4*>(&sB[kr][bn]) = b4;
        }
        __syncthreads();

#pragma unroll
        for (int k8 = 0; k8 < BK; k8 += 8) {
            unsigned a[2][4];
#pragma unroll
            for (int f = 0; f < 2; f++) {
                int r0 = wm + f * 16 + gid;
                a[f][0] = __float_as_uint(sA[k8 + tg    ][r0    ]);
                a[f][1] = __float_as_uint(sA[k8 + tg    ][r0 + 8]);
                a[f][2] = __float_as_uint(sA[k8 + tg + 4][r0    ]);
                a[f][3] = __float_as_uint(sA[k8 + tg + 4][r0 + 8]);
            }
            unsigned b[2][2];
#pragma unroll
            for (int j = 0; j < 2; j++) {
                int c = wn + j * 8 + gid;
                b[j][0] = __float_as_uint(sB[k8 + tg    ][c]);
                b[j][1] = __float_as_uint(sB[k8 + tg + 4][c]);
            }
#pragma unroll
            for (int f = 0; f < 2; f++)
#pragma unroll
                for (int j = 0; j < 2; j++)
                    mma_tf32(acc[f][j], a[f], b[j]);
        }
        __syncthreads();
    }

#pragma unroll
    for (int f = 0; f < 2; f++) {
#pragma unroll
        for (int half = 0; half < 2; half++) {
            int rm = wm + f * 16 + gid + half * 8;
            int gm = m0 + rm;
            if (gm < rows) {
                int t = stok[rm];
                float* orow = out + (size_t)t * HID;
#pragma unroll
                for (int j = 0; j < 2; j++) {
                    int col = n0 + wn + j * 8 + 2 * tg;
                    atomicAdd(orow + col,     acc[f][j][half * 2 + 0]);
                    atomicAdd(orow + col + 1, acc[f][j][half * 2 + 1]);
                }
            }
        }
    }
}

// ---------------------------------------------------------------------------
// launch
// ---------------------------------------------------------------------------
extern "C" void kernel_launch(void* const* d_in, const int* in_sizes, int n_in,
                              void* d_out, int out_size) {
    const float* x     = (const float*)d_in[0];
    const float* wgate = (const float*)d_in[1];
    const float* Wg    = (const float*)d_in[2];
    const float* Wu    = (const float*)d_in[3];
    const float* Wd    = (const float*)d_in[4];
    float* out = (float*)d_out;

    int n4 = (T_TOK * HID) / 4;
    init_kernel<<<(n4 + 255) / 256, 256>>>(out, n4);

    router_kernel<<<T_TOK, 256>>>(x, wgate);

    dim3 g1(INTER / BN, T_TOK / BM, NEXP);
    gemm1_kernel<<<g1, 256>>>(x, Wg, Wu);

    dim3 g2(HID / BN, T_TOK / BM, NEXP);
    gemm2_kernel<<<g2, 256>>>(Wd, out);
}

// round 4
// speedup vs baseline: 1.9299x; 1.0886x over previous
#include <cuda_runtime.h>

// Problem constants
#define T_TOK 2048
#define HID   2048
#define INTER 768
#define NEXP  8

#define BK   32
// gemm1 block: 128 x 64, gemm2 block: 128 x 128
#define BM   128
#define SAP  (BM + 8)    // sA stride (k-major, padded)
#define SG1P (64 + 8)    // gemm1 B stride
#define SB2P (128 + 8)   // gemm2 B stride

// Static device scratch
__device__ int   g_cnt[NEXP];
__device__ int   g_tok[NEXP * T_TOK];
__device__ float g_wt [NEXP * T_TOK];
__device__ float g_hc [(size_t)NEXP * T_TOK * INTER];

__device__ __forceinline__ float to_tf32(float x) {
    float y;
    asm("cvt.rna.tf32.f32 %0, %1;" : "=f"(y) : "f"(x));
    return y;
}

__device__ __forceinline__ void mma_tf32(float* d, const unsigned* a, const unsigned* b) {
    asm volatile(
        "mma.sync.aligned.m16n8k8.row.col.f32.tf32.tf32.f32 "
        "{%0,%1,%2,%3},{%4,%5,%6,%7},{%8,%9},{%0,%1,%2,%3};"
        : "+f"(d[0]), "+f"(d[1]), "+f"(d[2]), "+f"(d[3])
        : "r"(a[0]), "r"(a[1]), "r"(a[2]), "r"(a[3]), "r"(b[0]), "r"(b[1]));
}

// ---------------------------------------------------------------------------
__global__ void init_kernel(float* __restrict__ out, int n4) {
    int i = blockIdx.x * blockDim.x + threadIdx.x;
    if (i < n4) reinterpret_cast<float4*>(out)[i] = make_float4(0.f, 0.f, 0.f, 0.f);
    if (i < NEXP) g_cnt[i] = 0;
}

// ---------------------------------------------------------------------------
// router (exact fp32)
// ---------------------------------------------------------------------------
__global__ void router_kernel(const float* __restrict__ x,
                              const float* __restrict__ wgate) {
    const int t = blockIdx.x;
    const int tid = threadIdx.x;
    const float* xr = x + (size_t)t * HID;

    float part[NEXP];
#pragma unroll
    for (int e = 0; e < NEXP; e++) part[e] = 0.f;

    for (int h = tid; h < HID; h += 256) {
        float xv = xr[h];
#pragma unroll
        for (int e = 0; e < NEXP; e++)
            part[e] += xv * __ldg(&wgate[e * HID + h]);
    }

    __shared__ float red[256];
    __shared__ float logits[NEXP];
#pragma unroll
    for (int e = 0; e < NEXP; e++) {
        red[tid] = part[e];
        __syncthreads();
        for (int s = 128; s > 0; s >>= 1) {
            if (tid < s) red[tid] += red[tid + s];
            __syncthreads();
        }
        if (tid == 0) logits[e] = red[0];
        __syncthreads();
    }

    if (tid == 0) {
        float mx = logits[0];
#pragma unroll
        for (int e = 1; e < NEXP; e++) mx = fmaxf(mx, logits[e]);
        float p[NEXP], s = 0.f;
#pragma unroll
        for (int e = 0; e < NEXP; e++) { p[e] = expf(logits[e] - mx); s += p[e]; }
        float inv = 1.f / s;
#pragma unroll
        for (int e = 0; e < NEXP; e++) p[e] *= inv;

        int e1 = 0;
#pragma unroll
        for (int e = 1; e < NEXP; e++) if (p[e] > p[e1]) e1 = e;
        int e2 = (e1 == 0) ? 1 : 0;
#pragma unroll
        for (int e = 0; e < NEXP; e++)
            if (e != e1 && p[e] > p[e2]) e2 = e;

        float w1 = p[e1], w2 = p[e2];
        float rs = 1.f / (w1 + w2);
        w1 *= rs; w2 *= rs;

        int s1 = atomicAdd(&g_cnt[e1], 1);
        g_tok[e1 * T_TOK + s1] = t;
        g_wt [e1 * T_TOK + s1] = w1;
        int s2 = atomicAdd(&g_cnt[e2], 1);
        g_tok[e2 * T_TOK + s2] = t;
        g_wt [e2 * T_TOK + s2] = w2;
    }
}

// ---------------------------------------------------------------------------
// gemm1: block 128x64, 4 warps (2m x 2n), warp tile 64x32, dual G/U
// ---------------------------------------------------------------------------
__global__ __launch_bounds__(128) void gemm1_kernel(
    const float* __restrict__ x,
    const float* __restrict__ Wg,
    const float* __restrict__ Wu) {
    const int e = blockIdx.z;
    const int rows = g_cnt[e];
    const int m0 = blockIdx.y * BM;
    if (m0 >= rows) return;
    const int n0 = blockIdx.x * 64;

    __shared__ __align__(16) float sA[BK][SAP];
    __shared__ __align__(16) float sG[BK][SG1P];
    __shared__ __align__(16) float sU[BK][SG1P];
    __shared__ int   stok[BM];
    __shared__ float swt[BM];

    const int tid = threadIdx.x;
    {
        int gm = m0 + tid;
        int tk = 0; float w = 0.f;
        if (gm < rows) { tk = g_tok[e * T_TOK + gm]; w = g_wt[e * T_TOK + gm]; }
        stok[tid] = tk; swt[tid] = w;
    }
    __syncthreads();

    const float* xrow = x + (size_t)stok[tid] * HID;
    const float* wgB = Wg + (size_t)e * HID * INTER + n0;
    const float* wuB = Wu + (size_t)e * HID * INTER + n0;

    const int lane = tid & 31;
    const int warp = tid >> 5;
    const int wm = (warp & 1) * 64;
    const int wn = (warp >> 1) * 32;
    const int gid = lane >> 2, tg = lane & 3;

    const int bkr = tid >> 4;          // 0..7
    const int bcol = (tid & 15) * 4;   // 0..60

    float accG[4][4][4] = {};
    float accU[4][4][4] = {};

    for (int kk = 0; kk < HID; kk += BK) {
        // A: own token row, 32 k-values, transpose into sA[k][m]
#pragma unroll
        for (int q = 0; q < 8; q++) {
            float4 v = *reinterpret_cast<const float4*>(xrow + kk + q * 4);
            sA[q * 4 + 0][tid] = to_tf32(v.x);
            sA[q * 4 + 1][tid] = to_tf32(v.y);
            sA[q * 4 + 2][tid] = to_tf32(v.z);
            sA[q * 4 + 3][tid] = to_tf32(v.w);
        }
        // B tiles 32x64 each
#pragma unroll
        for (int s = 0; s < 4; s++) {
            int kr = bkr + s * 8;
            float4 g4 = *reinterpret_cast<const float4*>(wgB + (size_t)(kk + kr) * INTER + bcol);
            float4 u4 = *reinterpret_cast<const float4*>(wuB + (size_t)(kk + kr) * INTER + bcol);
            g4.x = to_tf32(g4.x); g4.y = to_tf32(g4.y); g4.z = to_tf32(g4.z); g4.w = to_tf32(g4.w);
            u4.x = to_tf32(u4.x); u4.y = to_tf32(u4.y); u4.z = to_tf32(u4.z); u4.w = to_tf32(u4.w);
            *reinterpret_cast<float4*>(&sG[kr][bcol]) = g4;
            *reinterpret_cast<float4*>(&sU[kr][bcol]) = u4;
        }
        __syncthreads();

#pragma unroll
        for (int k8 = 0; k8 < BK; k8 += 8) {
            unsigned a[4][4];
#pragma unroll
            for (int f = 0; f < 4; f++) {
                int r0 = wm + f * 16 + gid;
                a[f][0] = __float_as_uint(sA[k8 + tg    ][r0    ]);
                a[f][1] = __float_as_uint(sA[k8 + tg    ][r0 + 8]);
                a[f][2] = __float_as_uint(sA[k8 + tg + 4][r0    ]);
                a[f][3] = __float_as_uint(sA[k8 + tg + 4][r0 + 8]);
            }
            unsigned bg[4][2], bu[4][2];
#pragma unroll
            for (int j = 0; j < 4; j++) {
                int c = wn + j * 8 + gid;
                bg[j][0] = __float_as_uint(sG[k8 + tg    ][c]);
                bg[j][1] = __float_as_uint(sG[k8 + tg + 4][c]);
                bu[j][0] = __float_as_uint(sU[k8 + tg    ][c]);
                bu[j][1] = __float_as_uint(sU[k8 + tg + 4][c]);
            }
#pragma unroll
            for (int f = 0; f < 4; f++)
#pragma unroll
                for (int j = 0; j < 4; j++) {
                    mma_tf32(accG[f][j], a[f], bg[j]);
                    mma_tf32(accU[f][j], a[f], bu[j]);
                }
        }
        __syncthreads();
    }

    float* hbase = g_hc + (size_t)e * T_TOK * INTER;
#pragma unroll
    for (int f = 0; f < 4; f++) {
#pragma unroll
        for (int half = 0; half < 2; half++) {
            int rm = wm + f * 16 + gid + half * 8;
            int gm = m0 + rm;
            if (gm < rows) {
                float w = swt[rm];
#pragma unroll
                for (int j = 0; j < 4; j++) {
                    float g0 = accG[f][j][half * 2 + 0];
                    float g1 = accG[f][j][half * 2 + 1];
                    float u0 = accU[f][j][half * 2 + 0];
                    float u1 = accU[f][j][half * 2 + 1];
                    float s0 = g0 / (1.f + expf(-g0)) * u0 * w;
                    float s1 = g1 / (1.f + expf(-g1)) * u1 * w;
                    int col = n0 + wn + j * 8 + 2 * tg;
                    *reinterpret_cast<float2*>(hbase + (size_t)gm * INTER + col) =
                        make_float2(s0, s1);
                }
            }
        }
    }
}

// ---------------------------------------------------------------------------
// gemm2: block 128x128, 4 warps (2m x 2n), warp tile 64x64, atomic scatter
// ---------------------------------------------------------------------------
__global__ __launch_bounds__(128) void gemm2_kernel(
    const float* __restrict__ Wd,
    float* __restrict__ out) {
    const int e = blockIdx.z;
    const int rows = g_cnt[e];
    const int m0 = blockIdx.y * BM;
    if (m0 >= rows) return;
    const int n0 = blockIdx.x * 128;

    __shared__ __align__(16) float sA[BK][SAP];
    __shared__ __align__(16) float sB[BK][SB2P];
    __shared__ int stok[BM];

    const int tid = threadIdx.x;
    {
        int gm = m0 + tid;
        stok[tid] = (gm < rows) ? g_tok[e * T_TOK + gm] : 0;
    }
    __syncthreads();

    int arow_idx = m0 + tid;
    if (arow_idx >= rows) arow_idx = rows - 1;   // clamp: safe read, epilogue guarded
    const float* arow = g_hc + ((size_t)e * T_TOK + arow_idx) * INTER;
    const float* wdB = Wd + (size_t)e * INTER * HID + n0;

    const int lane = tid & 31;
    const int warp = tid >> 5;
    const int wm = (warp & 1) * 64;
    const int wn = (warp >> 1) * 64;
    const int gid = lane >> 2, tg = lane & 3;

    const int bkr = tid >> 5;          // 0..3
    const int bcol = (tid & 31) * 4;   // 0..124

    float acc[4][8][4] = {};

    for (int kk = 0; kk < INTER; kk += BK) {
#pragma unroll
        for (int q = 0; q < 8; q++) {
            float4 v = *reinterpret_cast<const float4*>(arow + kk + q * 4);
            sA[q * 4 + 0][tid] = to_tf32(v.x);
            sA[q * 4 + 1][tid] = to_tf32(v.y);
            sA[q * 4 + 2][tid] = to_tf32(v.z);
            sA[q * 4 + 3][tid] = to_tf32(v.w);
        }
#pragma unroll
        for (int s = 0; s < 8; s++) {
            int kr = bkr + s * 4;
            float4 b4 = *reinterpret_cast<const float4*>(wdB + (size_t)(kk + kr) * HID + bcol);
            b4.x = to_tf32(b4.x); b4.y = to_tf32(b4.y); b4.z = to_tf32(b4.z); b4.w = to_tf32(b4.w);
            *reinterpret_cast<float4*>(&sB[kr][bcol]) = b4;
        }
        __syncthreads();

#pragma unroll
        for (int k8 = 0; k8 < BK; k8 += 8) {
            unsigned a[4][4];
#pragma unroll
            for (int f = 0; f < 4; f++) {
                int r0 = wm + f * 16 + gid;
                a[f][0] = __float_as_uint(sA[k8 + tg    ][r0    ]);
                a[f][1] = __float_as_uint(sA[k8 + tg    ][r0 + 8]);
                a[f][2] = __float_as_uint(sA[k8 + tg + 4][r0    ]);
                a[f][3] = __float_as_uint(sA[k8 + tg + 4][r0 + 8]);
            }
            unsigned b[8][2];
#pragma unroll
            for (int j = 0; j < 8; j++) {
                int c = wn + j * 8 + gid;
                b[j][0] = __float_as_uint(sB[k8 + tg    ][c]);
                b[j][1] = __float_as_uint(sB[k8 + tg + 4][c]);
            }
#pragma unroll
            for (int f = 0; f < 4; f++)
#pragma unroll
                for (int j = 0; j < 8; j++)
                    mma_tf32(acc[f][j], a[f], b[j]);
        }
        __syncthreads();
    }

#pragma unroll
    for (int f = 0; f < 4; f++) {
#pragma unroll
        for (int half = 0; half < 2; half++) {
            int rm = wm + f * 16 + gid + half * 8;
            int gm = m0 + rm;
            if (gm < rows) {
                int t = stok[rm];
                float* orow = out + (size_t)t * HID;
#pragma unroll
                for (int j = 0; j < 8; j++) {
                    int col = n0 + wn + j * 8 + 2 * tg;
                    atomicAdd(orow + col,     acc[f][j][half * 2 + 0]);
                    atomicAdd(orow + col + 1, acc[f][j][half * 2 + 1]);
                }
            }
        }
    }
}

// ---------------------------------------------------------------------------
extern "C" void kernel_launch(void* const* d_in, const int* in_sizes, int n_in,
                              void* d_out, int out_size) {
    const float* x     = (const float*)d_in[0];
    const float* wgate = (const float*)d_in[1];
    const float* Wg    = (const float*)d_in[2];
    const float* Wu    = (const float*)d_in[3];
    const float* Wd    = (const float*)d_in[4];
    float* out = (float*)d_out;

    int n4 = (T_TOK * HID) / 4;
    init_kernel<<<(n4 + 255) / 256, 256>>>(out, n4);

    router_kernel<<<T_TOK, 256>>>(x, wgate);

    dim3 g1(INTER / 64, T_TOK / BM, NEXP);
    gemm1_kernel<<<g1, 128>>>(x, Wg, Wu);

    dim3 g2(HID / 128, T_TOK / BM, NEXP);
    gemm2_kernel<<<g2, 128>>>(Wd, out);
}